// round 11
// baseline (speedup 1.0000x reference)
#include <cuda_runtime.h>
#include <cuda_fp16.h>
#include <cstdint>

// ---------------------------------------------------------------------------
// Problem constants
// ---------------------------------------------------------------------------
constexpr int N_NODES = 50000;
constexpr int K_NBR   = 32;
constexpr int F_IN    = 64;
constexpr int F_OUT   = 64;
constexpr int BM      = 128;                       // nodes per CTA tile
constexpr int NBLK    = (N_NODES + BM - 1) / BM;   // 391

// Padded row stride: 72 fp16 = 144 B -> conflict-free ldmatrix & STS.128.
constexpr int RS   = 72;
constexpr int RSB  = RS * 2;              // 144 B
constexpr int A_TILE = BM * RSB;          // 18432 B
constexpr int B_TILE = F_IN * RSB;        //  9216 B
constexpr int BUFSZ  = A_TILE + B_TILE;   // 27648 B
constexpr int INV_OFF    = 2 * BUFSZ;     // 55296
constexpr int INV_STRIDE = 33;            // bank (r+k)%32 -> conflict-free
constexpr int SMEM_BYTES = INV_OFF + BM * INV_STRIDE * 4;   // 72192 B

// ---------------------------------------------------------------------------
// Device scratch: fp16 W^T tiles and fp16 copy of h
// ---------------------------------------------------------------------------
__device__ uint4 g_Wh4[K_NBR * (B_TILE / 16)];
__device__ uint4 g_Hh4[(size_t)N_NODES * F_IN * 2 / 16];   // 6.4 MB

// ---------------------------------------------------------------------------
// PTX helpers (baseline PTX — valid at virtual target sm_103)
// ---------------------------------------------------------------------------
__device__ __forceinline__ uint32_t smem_u32(const void* p) {
    uint32_t a;
    asm("{ .reg .u64 t; cvta.to.shared.u64 t, %1; cvt.u32.u64 %0, t; }"
        : "=r"(a) : "l"(p));
    return a;
}
#define LDM_X4(r, addr) \
    asm volatile("ldmatrix.sync.aligned.m8n8.x4.shared.b16 {%0,%1,%2,%3}, [%4];" \
        : "=r"((r)[0]), "=r"((r)[1]), "=r"((r)[2]), "=r"((r)[3]) : "r"(addr))
#define LDM_X4T(r, addr) \
    asm volatile("ldmatrix.sync.aligned.m8n8.x4.trans.shared.b16 {%0,%1,%2,%3}, [%4];" \
        : "=r"((r)[0]), "=r"((r)[1]), "=r"((r)[2]), "=r"((r)[3]) : "r"(addr))
#define MMA16816(d, a, b0, b1) \
    asm volatile("mma.sync.aligned.m16n8k16.row.col.f32.f16.f16.f32 " \
        "{%0,%1,%2,%3}, {%4,%5,%6,%7}, {%8,%9}, {%0,%1,%2,%3};" \
        : "+f"((d)[0]), "+f"((d)[1]), "+f"((d)[2]), "+f"((d)[3]) \
        : "r"((a)[0]), "r"((a)[1]), "r"((a)[2]), "r"((a)[3]), "r"(b0), "r"(b1))
#define CP_ASYNC16(dst, src) \
    asm volatile("cp.async.cg.shared.global [%0], [%1], 16;" \
        :: "r"(dst), "l"(src) : "memory")
#define CP_COMMIT()  asm volatile("cp.async.commit_group;" ::: "memory")
#define CP_WAIT0()   asm volatile("cp.async.wait_group 0;" ::: "memory")

// ---------------------------------------------------------------------------
// Kernel 1: combined conversions.
//   idx < N*F_IN/4      : h -> fp16 (vectorized)
//   idx < K*F_IN*F_OUT/4 also handled: W -> fp16 transposed [nbr][k][n] padded
// ---------------------------------------------------------------------------
__global__ __launch_bounds__(256) void convert_kernel(
    const float* __restrict__ h, const float* __restrict__ W)
{
    int i = blockIdx.x * blockDim.x + threadIdx.x;
    if (i < N_NODES * F_IN / 4) {
        float4 v = ((const float4*)h)[i];
        __half2 a = __floats2half2_rn(v.x, v.y);
        __half2 b = __floats2half2_rn(v.z, v.w);
        ((uint2*)g_Hh4)[i] = make_uint2(*(uint32_t*)&a, *(uint32_t*)&b);
    }
    if (i < K_NBR * F_IN * F_OUT / 4) {
        // 4 consecutive n-values of one (nbr, kk) row
        int nbr = i >> 10;
        int kk  = (i >> 4) & 63;
        int n4  = (i & 15) * 4;
        float4 w = *(const float4*)(W + (((size_t)nbr * F_IN + kk) * F_OUT + n4));
        __half2 a = __floats2half2_rn(w.x, w.y);
        __half2 b = __floats2half2_rn(w.z, w.w);
        *(uint2*)((__half*)g_Wh4 + ((size_t)nbr * F_IN + kk) * RS + n4) =
            make_uint2(*(uint32_t*)&a, *(uint32_t*)&b);
    }
}

// ---------------------------------------------------------------------------
// Kernel 2: fused gather-scale-GEMM. 128 threads = 4 warps of 64x32 tiles
// (2 m-bands x 2 n-bands) -> fragment duplication A x2, B x2 (48 KB/iter).
// Steady state: nbr idx 2 iters ahead, h-row 1 iter ahead (regs), B cp.async.
// ---------------------------------------------------------------------------
extern __shared__ uint8_t dynsmem[];

__global__ __launch_bounds__(128, 3) void gnn_mma_kernel(
    const int* __restrict__ nidx, const float* __restrict__ pos,
    const float* __restrict__ bias, float* __restrict__ out)
{
    const int tid = threadIdx.x;
    const int wid = tid >> 5;
    const int lid = tid & 31;
    const int node0 = blockIdx.x * BM;

    const uint32_t sbase = smem_u32(dynsmem);
    float* invS = (float*)(dynsmem + INV_OFF);

    // Staging role: 1 thread per node row
    const int r = tid;
    const int grow = node0 + r;
    const bool ok = (grow < N_NODES);
    const int* nrow = nidx + (size_t)grow * K_NBR;

    // ---- prologue: all 32 inverse distances for this row ----
    {
        float pix = 0.f, piy = 0.f, piz = 0.f;
        if (ok) {
            pix = pos[(size_t)grow * 3 + 0];
            piy = pos[(size_t)grow * 3 + 1];
            piz = pos[(size_t)grow * 3 + 2];
        }
#pragma unroll 4
        for (int k = 0; k < K_NBR; ++k) {
            float inv = 0.0f;
            if (ok) {
                int nbr = nrow[k];
                float dx = pix - pos[(size_t)nbr * 3 + 0];
                float dy = piy - pos[(size_t)nbr * 3 + 1];
                float dz = piz - pos[(size_t)nbr * 3 + 2];
                float sq = fmaf(dx, dx, fmaf(dy, dy, dz * dz));
                inv = (sq == 0.0f) ? 2.0f : rsqrtf(sq);   // dist==0 -> 0.5
            }
            invS[r * INV_STRIDE + k] = inv;
        }
    }
    __syncthreads();

    uint8_t* AdstBase = dynsmem + r * RSB;
    auto scale_sts = [&](const uint4* hv, int kn, int buf) {
        __half2 inv2 = __float2half2_rn(invS[r * INV_STRIDE + kn]);
        uint8_t* dst = AdstBase + buf * BUFSZ;
#pragma unroll
        for (int j = 0; j < 8; ++j) {
            uint4 v = hv[j];
            __half2* p = (__half2*)&v;
            p[0] = __hmul2(p[0], inv2);
            p[1] = __hmul2(p[1], inv2);
            p[2] = __hmul2(p[2], inv2);
            p[3] = __hmul2(p[3], inv2);
            *(uint4*)(dst + j * 16) = v;
        }
    };
    auto stageB = [&](int k, int buf) {
        const uint4* src = g_Wh4 + (size_t)k * (B_TILE / 16);
        uint32_t dst = sbase + buf * BUFSZ + A_TILE;
#pragma unroll
        for (int j = 0; j < 4; ++j)
            CP_ASYNC16(dst + (tid + j * 128) * 16, (const void*)(src + tid + j * 128));
        if (tid < B_TILE / 16 - 512)
            CP_ASYNC16(dst + (tid + 512) * 16, (const void*)(src + tid + 512));
        CP_COMMIT();
    };

    // ---- prologue: stage k=0 ----
    {
        int nbr0 = ok ? nrow[0] : 0;
        uint4 hv[8];
        const uint4* hs = g_Hh4 + (size_t)nbr0 * 8;
#pragma unroll
        for (int j = 0; j < 8; ++j) hv[j] = hs[j];
        scale_sts(hv, 0, 0);
        stageB(0, 0);
    }
    int nbr_cur = ok ? nrow[1] : 0;
    CP_WAIT0();
    __syncthreads();

    // MMA addressing: warp tile 64 rows x 32 cols
    const uint32_t mrow = (wid >> 1) * 64;
    const uint32_t ncol = (wid & 1) * 32;
    const uint32_t lrow = (lid & 15);
    const uint32_t loff = (lid >> 4) * 16;
    const uint32_t aOff = (mrow + lrow) * RSB + loff;
    const uint32_t bOff = A_TILE + lrow * RSB + ncol * 2 + loff;

    float acc[4][4][4];   // [m16 tile][n8 tile][frag]
#pragma unroll
    for (int t = 0; t < 4; ++t)
#pragma unroll
        for (int i = 0; i < 4; ++i)
#pragma unroll
            for (int j = 0; j < 4; ++j) acc[t][i][j] = 0.0f;

    for (int k = 0; k < K_NBR; ++k) {
        const int buf = k & 1;
        const int kn  = k + 1;

        // prefetch A row (k+1) into regs; B (k+1) via cp.async; nbr (k+2)
        uint4 hvn[8];
        if (kn < K_NBR) {
            const uint4* hs = g_Hh4 + (size_t)nbr_cur * 8;
#pragma unroll
            for (int j = 0; j < 8; ++j) hvn[j] = hs[j];
            stageB(kn, buf ^ 1);
        }
        int nbr_nx = (k + 2 < K_NBR && ok) ? nrow[k + 2] : 0;

        // MMA on buf (neighbor k): 4 kc x (4 m16 x 4 n8)
        const uint32_t ab = sbase + buf * BUFSZ;
#pragma unroll
        for (int kc = 0; kc < 4; ++kc) {
            uint32_t a[4][4];
#pragma unroll
            for (int mt = 0; mt < 4; ++mt)
                LDM_X4(a[mt], ab + aOff + mt * 16 * RSB + kc * 32);
#pragma unroll
            for (int g2 = 0; g2 < 2; ++g2) {
                uint32_t b[4];
                LDM_X4T(b, ab + bOff + g2 * 32 + kc * 16 * RSB);
#pragma unroll
                for (int mt = 0; mt < 4; ++mt) {
                    MMA16816(acc[mt][g2 * 2 + 0], a[mt], b[0], b[1]);
                    MMA16816(acc[mt][g2 * 2 + 1], a[mt], b[2], b[3]);
                }
            }
        }

        if (kn < K_NBR) scale_sts(hvn, kn, buf ^ 1);
        nbr_cur = nbr_nx;

        CP_WAIT0();
        __syncthreads();
    }

    // ---- epilogue: bias + leaky_relu(0.01) ----
    const int g  = lid >> 2;
    const int c0 = (lid & 3) * 2;
#pragma unroll
    for (int mt = 0; mt < 4; ++mt) {
        const int row0 = node0 + mrow + mt * 16 + g;
        const int row1 = row0 + 8;
#pragma unroll
        for (int nt = 0; nt < 4; ++nt) {
            int col = ncol + nt * 8 + c0;
            float bx = bias[col], by = bias[col + 1];
            float2 v0 = make_float2(acc[mt][nt][0] + bx, acc[mt][nt][1] + by);
            float2 v1 = make_float2(acc[mt][nt][2] + bx, acc[mt][nt][3] + by);
            v0.x = (v0.x > 0.0f) ? v0.x : 0.01f * v0.x;
            v0.y = (v0.y > 0.0f) ? v0.y : 0.01f * v0.y;
            v1.x = (v1.x > 0.0f) ? v1.x : 0.01f * v1.x;
            v1.y = (v1.y > 0.0f) ? v1.y : 0.01f * v1.y;
            if (row0 < N_NODES) *(float2*)(out + (size_t)row0 * F_OUT + col) = v0;
            if (row1 < N_NODES) *(float2*)(out + (size_t)row1 * F_OUT + col) = v1;
        }
    }
}

// ---------------------------------------------------------------------------
// Harness entry. Inputs: h, pos, neighbor_idx, weight, bias_p
// ---------------------------------------------------------------------------
extern "C" void kernel_launch(void* const* d_in, const int* in_sizes, int n_in,
                              void* d_out, int out_size)
{
    const float* h    = (const float*)d_in[0];
    const float* pos  = (const float*)d_in[1];
    const int*   nidx = (const int*)d_in[2];
    const float* W    = (const float*)d_in[3];
    const float* bias = (const float*)d_in[4];
    float*       out  = (float*)d_out;

    static bool attr_set = false;
    if (!attr_set) {
        cudaFuncSetAttribute(gnn_mma_kernel,
                             cudaFuncAttributeMaxDynamicSharedMemorySize, SMEM_BYTES);
        attr_set = true;
    }

    convert_kernel<<<(N_NODES * F_IN / 4 + 255) / 256, 256>>>(h, W);
    gnn_mma_kernel<<<NBLK, 128, SMEM_BYTES>>>(nidx, pos, bias, out);
}

// round 14
// speedup vs baseline: 1.0478x; 1.0478x over previous
#include <cuda_runtime.h>
#include <cuda_fp16.h>
#include <cstdint>

// ---------------------------------------------------------------------------
// Problem constants
// ---------------------------------------------------------------------------
constexpr int N_NODES = 50000;
constexpr int K_NBR   = 32;
constexpr int F_IN    = 64;
constexpr int F_OUT   = 64;
constexpr int BM      = 128;
constexpr int NBLK    = (N_NODES + BM - 1) / BM;   // 391

// Padded row stride: 72 fp16 = 144 B -> conflict-free ldmatrix & 2-way-max STS.
constexpr int RS   = 72;
constexpr int RSB  = RS * 2;              // 144 B
constexpr int A_TILE = BM * RSB;          // 18432 B
constexpr int B_TILE = F_IN * RSB;        //  9216 B

// smem layout: Atile[2], Btile[2], rawA[2] (unscaled gathered h rows, padded
// stride), posbuf[2] (16 B per row)
constexpr int SM_A    = 0;                        // 2 x 18432
constexpr int SM_B    = SM_A + 2 * A_TILE;        // 36864, 2 x 9216
constexpr int SM_RAW  = SM_B + 2 * B_TILE;        // 55296, 2 x 18432
constexpr int SM_POS  = SM_RAW + 2 * A_TILE;      // 92160, 2 x 2048
constexpr int SMEM_BYTES = SM_POS + 2 * 2048;     // 96256

// ---------------------------------------------------------------------------
// Device scratch: fp16 W^T tiles and fp16 copy of h
// ---------------------------------------------------------------------------
__device__ uint4 g_Wh4[K_NBR * (B_TILE / 16)];
__device__ uint4 g_Hh4[(size_t)N_NODES * F_IN * 2 / 16];   // 6.4 MB

// ---------------------------------------------------------------------------
// PTX helpers (baseline PTX — valid at virtual target sm_103)
// ---------------------------------------------------------------------------
__device__ __forceinline__ uint32_t smem_u32(const void* p) {
    uint32_t a;
    asm("{ .reg .u64 t; cvta.to.shared.u64 t, %1; cvt.u32.u64 %0, t; }"
        : "=r"(a) : "l"(p));
    return a;
}
#define LDM_X4(r, addr) \
    asm volatile("ldmatrix.sync.aligned.m8n8.x4.shared.b16 {%0,%1,%2,%3}, [%4];" \
        : "=r"((r)[0]), "=r"((r)[1]), "=r"((r)[2]), "=r"((r)[3]) : "r"(addr))
#define LDM_X4T(r, addr) \
    asm volatile("ldmatrix.sync.aligned.m8n8.x4.trans.shared.b16 {%0,%1,%2,%3}, [%4];" \
        : "=r"((r)[0]), "=r"((r)[1]), "=r"((r)[2]), "=r"((r)[3]) : "r"(addr))
#define MMA16816(d, a, b0, b1) \
    asm volatile("mma.sync.aligned.m16n8k16.row.col.f32.f16.f16.f32 " \
        "{%0,%1,%2,%3}, {%4,%5,%6,%7}, {%8,%9}, {%0,%1,%2,%3};" \
        : "+f"((d)[0]), "+f"((d)[1]), "+f"((d)[2]), "+f"((d)[3]) \
        : "r"((a)[0]), "r"((a)[1]), "r"((a)[2]), "r"((a)[3]), "r"(b0), "r"(b1))
#define CP_ASYNC16(dst, src) \
    asm volatile("cp.async.cg.shared.global [%0], [%1], 16;" \
        :: "r"(dst), "l"(src) : "memory")
#define CP_ASYNC4(dst, src) \
    asm volatile("cp.async.ca.shared.global [%0], [%1], 4;" \
        :: "r"(dst), "l"(src) : "memory")
#define CP_COMMIT()  asm volatile("cp.async.commit_group;" ::: "memory")
#define CP_WAIT0()   asm volatile("cp.async.wait_group 0;" ::: "memory")
#define CP_WAIT1()   asm volatile("cp.async.wait_group 1;" ::: "memory")

// ---------------------------------------------------------------------------
// Kernel 1: combined conversions (h -> fp16; W -> fp16 transposed+padded)
// ---------------------------------------------------------------------------
__global__ __launch_bounds__(256) void convert_kernel(
    const float* __restrict__ h, const float* __restrict__ W)
{
    int i = blockIdx.x * blockDim.x + threadIdx.x;
    if (i < N_NODES * F_IN / 4) {
        float4 v = ((const float4*)h)[i];
        __half2 a = __floats2half2_rn(v.x, v.y);
        __half2 b = __floats2half2_rn(v.z, v.w);
        ((uint2*)g_Hh4)[i] = make_uint2(*(uint32_t*)&a, *(uint32_t*)&b);
    }
    if (i < K_NBR * F_IN * F_OUT / 4) {
        int nbr = i >> 10;
        int kk  = (i >> 4) & 63;
        int n4  = (i & 15) * 4;
        float4 w = *(const float4*)(W + (((size_t)nbr * F_IN + kk) * F_OUT + n4));
        __half2 a = __floats2half2_rn(w.x, w.y);
        __half2 b = __floats2half2_rn(w.z, w.w);
        *(uint2*)((__half*)g_Wh4 + ((size_t)nbr * F_IN + kk) * RS + n4) =
            make_uint2(*(uint32_t*)&a, *(uint32_t*)&b);
    }
}

// ---------------------------------------------------------------------------
// Kernel 2: fused gather-scale-GEMM. 256 threads = 8 warps (4m x 2n of 32x32).
// All global traffic for phase k+1 (gathered h rows, neighbor pos, W tile)
// goes through cp.async issued at the top of phase k -> one full MMA phase to
// land; barriers only fence deterministic smem work.
// Phase k: issue(k+1) | wait_group(1) | scale(k): raw->inv->A-tile | sync |
//          MMA(k) | sync.
// ---------------------------------------------------------------------------
extern __shared__ uint8_t dynsmem[];

__global__ __launch_bounds__(256, 2) void gnn_mma_kernel(
    const int* __restrict__ nidx, const float* __restrict__ pos,
    const float* __restrict__ bias, float* __restrict__ out)
{
    const int tid = threadIdx.x;
    const int wid = tid >> 5;
    const int lid = tid & 31;
    const int node0 = blockIdx.x * BM;

    const uint32_t sbase = smem_u32(dynsmem);

    // Staging roles: row r = tid>>1, half hh = tid&1 (64 B of the 128 B row)
    const int r  = tid >> 1;
    const int hh = tid & 1;
    const int grow = node0 + r;
    const bool ok = (grow < N_NODES);
    const int* nrow = nidx + (size_t)grow * K_NBR;

    float pix = 0.f, piy = 0.f, piz = 0.f;
    if (ok) {
        pix = pos[(size_t)grow * 3 + 0];
        piy = pos[(size_t)grow * 3 + 1];
        piz = pos[(size_t)grow * 3 + 2];
    }

    // cp.async issue for phase kk (raw h rows + pos + B tile), buffer parity p
    auto issue_stage = [&](int nbr_k, int kk, int p) {
        const char* hsrc = (const char*)(g_Hh4 + (size_t)nbr_k * 8) + hh * 64;
        uint32_t rdst = sbase + SM_RAW + p * A_TILE + r * RSB + hh * 64;
#pragma unroll
        for (int j = 0; j < 4; ++j)
            CP_ASYNC16(rdst + j * 16, hsrc + j * 16);
        // pos: three 4-byte copies (12B-strided source is only 4B-aligned)
        uint32_t pdst = sbase + SM_POS + p * 2048 + r * 16;
        const float* psrc = pos + (size_t)nbr_k * 3;
        if (hh == 0) {
            CP_ASYNC4(pdst,     psrc);
            CP_ASYNC4(pdst + 4, psrc + 1);
        } else {
            CP_ASYNC4(pdst + 8, psrc + 2);
        }
        // B tile: 576 x 16B, 256 threads
        const uint4* bsrc = g_Wh4 + (size_t)kk * (B_TILE / 16);
        uint32_t bdst = sbase + SM_B + p * B_TILE;
        CP_ASYNC16(bdst + tid * 16,         (const char*)(bsrc + tid));
        CP_ASYNC16(bdst + (tid + 256) * 16, (const char*)(bsrc + tid + 256));
        if (tid < B_TILE / 16 - 512)
            CP_ASYNC16(bdst + (tid + 512) * 16, (const char*)(bsrc + tid + 512));
        CP_COMMIT();
    };

    // scale phase: raw(p) -> inv -> A-tile(p)
    auto scale_phase = [&](int p) {
        uint32_t praw = sbase + SM_POS + p * 2048 + r * 16;
        float nx, ny, nz;
        asm volatile("ld.shared.v2.f32 {%0, %1}, [%2];"
                     : "=f"(nx), "=f"(ny) : "r"(praw));
        asm volatile("ld.shared.f32 %0, [%1];" : "=f"(nz) : "r"(praw + 8));
        float inv = 0.0f;
        if (ok) {
            float dx = pix - nx, dy = piy - ny, dz = piz - nz;
            float sq = fmaf(dx, dx, fmaf(dy, dy, dz * dz));
            inv = (sq == 0.0f) ? 2.0f : rsqrtf(sq);   // dist==0 -> 0.5 -> inv 2
        }
        __half2 inv2 = __float2half2_rn(inv);
        uint32_t rsrc = sbase + SM_RAW + p * A_TILE + r * RSB + hh * 64;
        uint32_t adst = sbase + SM_A   + p * A_TILE + r * RSB + hh * 64;
#pragma unroll
        for (int j = 0; j < 4; ++j) {
            uint4 v;
            asm volatile("ld.shared.v4.b32 {%0,%1,%2,%3}, [%4];"
                         : "=r"(v.x), "=r"(v.y), "=r"(v.z), "=r"(v.w)
                         : "r"(rsrc + j * 16));
            __half2* ph = (__half2*)&v;
            ph[0] = __hmul2(ph[0], inv2);
            ph[1] = __hmul2(ph[1], inv2);
            ph[2] = __hmul2(ph[2], inv2);
            ph[3] = __hmul2(ph[3], inv2);
            asm volatile("st.shared.v4.b32 [%0], {%1,%2,%3,%4};"
                         :: "r"(adst + j * 16), "r"(v.x), "r"(v.y), "r"(v.z), "r"(v.w));
        }
    };

    // ---- prologue ----
    int nbr_cur = ok ? nrow[0] : 0;     // neighbor for phase 0
    issue_stage(nbr_cur, 0, 0);
    int nbr_nx = ok ? nrow[1] : 0;      // neighbor for phase 1

    // MMA addressing: warp tile 32 rows x 32 cols (4m x 2n)
    const uint32_t mrow = (wid >> 1) * 32;
    const uint32_t ncol = (wid & 1) * 32;
    const uint32_t lrow = (lid & 15);
    const uint32_t loff = (lid >> 4) * 16;
    const uint32_t aOff = SM_A + (mrow + lrow) * RSB + loff;
    const uint32_t bOff = SM_B + lrow * RSB + ncol * 2 + loff;

    float acc[2][4][4];
#pragma unroll
    for (int t = 0; t < 2; ++t)
#pragma unroll
        for (int i = 0; i < 4; ++i)
#pragma unroll
            for (int j = 0; j < 4; ++j) acc[t][i][j] = 0.0f;

    for (int k = 0; k < K_NBR; ++k) {
        const int p = k & 1;

        // issue stage for k+1 into parity p^1; prefetch nbr index k+2
        if (k + 1 < K_NBR) {
            issue_stage(nbr_nx, k + 1, p ^ 1);
            nbr_nx = (k + 2 < K_NBR && ok) ? nrow[k + 2] : 0;
            CP_WAIT1();                 // group(k) complete, group(k+1) in flight
        } else {
            CP_WAIT0();
        }

        scale_phase(p);
        __syncthreads();                // A-tile(p) visible; B(p) ready

        const uint32_t ab = sbase + p * A_TILE;   // A parity offset
        const uint32_t bb = sbase + p * B_TILE;   // B parity offset
#pragma unroll
        for (int kc = 0; kc < 4; ++kc) {
            uint32_t a0[4], a1[4];
            LDM_X4(a0, ab + aOff + kc * 32);
            LDM_X4(a1, ab + aOff + 16 * RSB + kc * 32);
#pragma unroll
            for (int g2 = 0; g2 < 2; ++g2) {
                uint32_t b[4];
                LDM_X4T(b, bb + bOff + g2 * 32 + kc * 16 * RSB);
                MMA16816(acc[0][g2 * 2 + 0], a0, b[0], b[1]);
                MMA16816(acc[0][g2 * 2 + 1], a0, b[2], b[3]);
                MMA16816(acc[1][g2 * 2 + 0], a1, b[0], b[1]);
                MMA16816(acc[1][g2 * 2 + 1], a1, b[2], b[3]);
            }
        }
        __syncthreads();                // MMA(k) done before buffers p reused
    }

    // ---- epilogue: bias + leaky_relu(0.01) ----
    const int g  = lid >> 2;
    const int c0 = (lid & 3) * 2;
#pragma unroll
    for (int t = 0; t < 2; ++t) {
        const int row0 = node0 + mrow + t * 16 + g;
        const int row1 = row0 + 8;
#pragma unroll
        for (int nt = 0; nt < 4; ++nt) {
            int col = ncol + nt * 8 + c0;
            float bx = bias[col], by = bias[col + 1];
            float2 v0 = make_float2(acc[t][nt][0] + bx, acc[t][nt][1] + by);
            float2 v1 = make_float2(acc[t][nt][2] + bx, acc[t][nt][3] + by);
            v0.x = (v0.x > 0.0f) ? v0.x : 0.01f * v0.x;
            v0.y = (v0.y > 0.0f) ? v0.y : 0.01f * v0.y;
            v1.x = (v1.x > 0.0f) ? v1.x : 0.01f * v1.x;
            v1.y = (v1.y > 0.0f) ? v1.y : 0.01f * v1.y;
            if (row0 < N_NODES) *(float2*)(out + (size_t)row0 * F_OUT + col) = v0;
            if (row1 < N_NODES) *(float2*)(out + (size_t)row1 * F_OUT + col) = v1;
        }
    }
}

// ---------------------------------------------------------------------------
// Harness entry. Inputs: h, pos, neighbor_idx, weight, bias_p
// ---------------------------------------------------------------------------
extern "C" void kernel_launch(void* const* d_in, const int* in_sizes, int n_in,
                              void* d_out, int out_size)
{
    const float* h    = (const float*)d_in[0];
    const float* pos  = (const float*)d_in[1];
    const int*   nidx = (const int*)d_in[2];
    const float* W    = (const float*)d_in[3];
    const float* bias = (const float*)d_in[4];
    float*       out  = (float*)d_out;

    static bool attr_set = false;
    if (!attr_set) {
        cudaFuncSetAttribute(gnn_mma_kernel,
                             cudaFuncAttributeMaxDynamicSharedMemorySize, SMEM_BYTES);
        attr_set = true;
    }

    convert_kernel<<<(N_NODES * F_IN / 4 + 255) / 256, 256>>>(h, W);
    gnn_mma_kernel<<<NBLK, 256, SMEM_BYTES>>>(nidx, pos, bias, out);
}

// round 15
// speedup vs baseline: 1.2957x; 1.2366x over previous
#include <cuda_runtime.h>
#include <cuda_fp16.h>
#include <cstdint>

// ---------------------------------------------------------------------------
// Problem constants
// ---------------------------------------------------------------------------
constexpr int N_NODES = 50000;
constexpr int K_NBR   = 32;
constexpr int F_IN    = 64;
constexpr int F_OUT   = 64;
constexpr int BM      = 128;
constexpr int NBLK    = (N_NODES + BM - 1) / BM;   // 391

// Padded row stride: 72 fp16 = 144 B -> conflict-free ldmatrix & STS.128.
constexpr int RS   = 72;
constexpr int RSB  = RS * 2;              // 144 B
constexpr int A_TILE = BM * RSB;          // 18432 B
constexpr int B_TILE = F_IN * RSB;        //  9216 B (frag kernel only)

constexpr int INV_OFF    = 2 * A_TILE;    // 36864
constexpr int INV_STRIDE = 33;
constexpr int SMEM_BYTES = INV_OFF + BM * INV_STRIDE * 4;   // 53760 B

// ---------------------------------------------------------------------------
// Device scratch
// ---------------------------------------------------------------------------
__device__ uint4 g_Hh4[(size_t)N_NODES * F_IN * 2 / 16];     // h as fp16, 6.4 MB
// B fragments in mma layout: [k][band][kc][g2][lane] -> uint4 (b0..b3)
__device__ uint4 g_Bfrag[K_NBR * 2 * 4 * 2 * 32];            // 256 KB

// ---------------------------------------------------------------------------
// PTX helpers (baseline PTX — valid at virtual target sm_103)
// ---------------------------------------------------------------------------
__device__ __forceinline__ uint32_t smem_u32(const void* p) {
    uint32_t a;
    asm("{ .reg .u64 t; cvta.to.shared.u64 t, %1; cvt.u32.u64 %0, t; }"
        : "=r"(a) : "l"(p));
    return a;
}
#define LDM_X4(r, addr) \
    asm volatile("ldmatrix.sync.aligned.m8n8.x4.shared.b16 {%0,%1,%2,%3}, [%4];" \
        : "=r"((r)[0]), "=r"((r)[1]), "=r"((r)[2]), "=r"((r)[3]) : "r"(addr))
#define LDM_X4T(r, addr) \
    asm volatile("ldmatrix.sync.aligned.m8n8.x4.trans.shared.b16 {%0,%1,%2,%3}, [%4];" \
        : "=r"((r)[0]), "=r"((r)[1]), "=r"((r)[2]), "=r"((r)[3]) : "r"(addr))
#define MMA16816(d, a, b0, b1) \
    asm volatile("mma.sync.aligned.m16n8k16.row.col.f32.f16.f16.f32 " \
        "{%0,%1,%2,%3}, {%4,%5,%6,%7}, {%8,%9}, {%0,%1,%2,%3};" \
        : "+f"((d)[0]), "+f"((d)[1]), "+f"((d)[2]), "+f"((d)[3]) \
        : "r"((a)[0]), "r"((a)[1]), "r"((a)[2]), "r"((a)[3]), "r"(b0), "r"(b1))

// ---------------------------------------------------------------------------
// Kernel 1: h -> fp16 (vectorized bulk convert)
// ---------------------------------------------------------------------------
__global__ __launch_bounds__(256) void convert_h_kernel(const float* __restrict__ h)
{
    int i = blockIdx.x * blockDim.x + threadIdx.x;
    if (i >= N_NODES * F_IN / 4) return;
    float4 v = ((const float4*)h)[i];
    __half2 a = __floats2half2_rn(v.x, v.y);
    __half2 b = __floats2half2_rn(v.z, v.w);
    ((uint2*)g_Hh4)[i] = make_uint2(*(uint32_t*)&a, *(uint32_t*)&b);
}

// ---------------------------------------------------------------------------
// Kernel 2: build B fragments. One CTA per neighbor k. Stage W[k] as fp16 in
// the SAME padded [kk][n] layout the main kernel used, then run the SAME
// ldmatrix.trans addressing and store each lane's uint4 fragment to global.
// Warp w handles (band = w&1, kc = w>>1); g2 in {0,1}.
// ---------------------------------------------------------------------------
__global__ __launch_bounds__(256) void frag_w_kernel(const float* __restrict__ W)
{
    __shared__ __align__(16) uint8_t btile[B_TILE];
    const int k   = blockIdx.x;
    const int tid = threadIdx.x;
    const int wid = tid >> 5;
    const int lid = tid & 31;

    // Stage: thread t converts 16 n-values of row kk = t>>2, n0 = (t&3)*16
    {
        const int kk = tid >> 2;
        const int n0 = (tid & 3) * 16;
        const float* src = W + (((size_t)k * F_IN + kk) * F_OUT + n0);
        uint32_t w[8];
#pragma unroll
        for (int j = 0; j < 4; ++j) {
            float4 v = *(const float4*)(src + j * 4);
            __half2 a = __floats2half2_rn(v.x, v.y);
            __half2 b = __floats2half2_rn(v.z, v.w);
            w[2 * j + 0] = *(uint32_t*)&a;
            w[2 * j + 1] = *(uint32_t*)&b;
        }
        uint8_t* dst = btile + kk * RSB + n0 * 2;
        *(uint4*)(dst)      = ((uint4*)w)[0];
        *(uint4*)(dst + 16) = ((uint4*)w)[1];
    }
    __syncthreads();

    // ldmatrix.trans with the proven addressing, then STG fragments
    const int band = wid & 1;
    const int kc   = wid >> 1;
    const uint32_t sb = smem_u32(btile);
    const uint32_t lrow = (lid & 15);
    const uint32_t loff = (lid >> 4) * 16;
    const uint32_t baseAddr = sb + lrow * RSB + band * 64 + loff + kc * 16 * RSB;
#pragma unroll
    for (int g2 = 0; g2 < 2; ++g2) {
        uint32_t b[4];
        LDM_X4T(b, baseAddr + g2 * 32);
        g_Bfrag[((((size_t)k * 2 + band) * 4 + kc) * 2 + g2) * 32 + lid] =
            make_uint4(b[0], b[1], b[2], b[3]);
    }
}

// ---------------------------------------------------------------------------
// Kernel 3: fused gather-scale-GEMM (R10 structure, B via direct frag LDG).
// 256 threads = 8 warps (4m x 2n of 32x32). Per iter: prefetch h(k+1) to regs,
// MMA(k) with B fragments LDG'd from L2, scale+STS A(k+1), one sync.
// ---------------------------------------------------------------------------
extern __shared__ uint8_t dynsmem[];

__global__ __launch_bounds__(256, 3) void gnn_mma_kernel(
    const int* __restrict__ nidx, const float* __restrict__ pos,
    const float* __restrict__ bias, float* __restrict__ out)
{
    const int tid = threadIdx.x;
    const int wid = tid >> 5;
    const int lid = tid & 31;
    const int node0 = blockIdx.x * BM;

    const uint32_t sbase = smem_u32(dynsmem);
    float* invS = (float*)(dynsmem + INV_OFF);

    // Staging roles: row r = tid>>1, half hh = tid&1
    const int r  = tid >> 1;
    const int hh = tid & 1;
    const int grow = node0 + r;
    const bool ok = (grow < N_NODES);
    const int* nrow = nidx + (size_t)grow * K_NBR;

    // ---- prologue: inverse distances (16 per thread) ----
    {
        float pix = 0.f, piy = 0.f, piz = 0.f;
        if (ok) {
            pix = pos[(size_t)grow * 3 + 0];
            piy = pos[(size_t)grow * 3 + 1];
            piz = pos[(size_t)grow * 3 + 2];
        }
#pragma unroll 4
        for (int kk = 0; kk < 16; ++kk) {
            int k = hh * 16 + kk;
            float inv = 0.0f;
            if (ok) {
                int nbr = nrow[k];
                float dx = pix - pos[(size_t)nbr * 3 + 0];
                float dy = piy - pos[(size_t)nbr * 3 + 1];
                float dz = piz - pos[(size_t)nbr * 3 + 2];
                float sq = fmaf(dx, dx, fmaf(dy, dy, dz * dz));
                inv = (sq == 0.0f) ? 2.0f : rsqrtf(sq);   // dist==0 -> 0.5
            }
            invS[r * INV_STRIDE + k] = inv;
        }
    }
    __syncthreads();

    uint8_t* AdstBase = dynsmem + r * RSB + hh * 64;
    auto scale_sts = [&](const uint4* hv, int kn, int buf) {
        __half2 inv2 = __float2half2_rn(invS[r * INV_STRIDE + kn]);
        uint8_t* dst = AdstBase + buf * A_TILE;
#pragma unroll
        for (int j = 0; j < 4; ++j) {
            uint4 v = hv[j];
            __half2* p = (__half2*)&v;
            p[0] = __hmul2(p[0], inv2);
            p[1] = __hmul2(p[1], inv2);
            p[2] = __hmul2(p[2], inv2);
            p[3] = __hmul2(p[3], inv2);
            *(uint4*)(dst + j * 16) = v;
        }
    };

    // ---- prologue: stage k=0 into buf 0 ----
    {
        int nbr0 = ok ? nrow[0] : 0;
        uint4 hv[4];
        const uint4* hs = g_Hh4 + (size_t)nbr0 * 8 + hh * 4;
#pragma unroll
        for (int j = 0; j < 4; ++j) hv[j] = hs[j];
        scale_sts(hv, 0, 0);
    }
    int nbr_cur = ok ? nrow[1] : 0;
    __syncthreads();

    // MMA addressing: warp tile 32 rows x 32 cols (4m x 2n)
    const int band = wid & 1;
    const uint32_t mrow = (wid >> 1) * 32;
    const uint32_t lrow = (lid & 15);
    const uint32_t loff = (lid >> 4) * 16;
    const uint32_t aOff = (mrow + lrow) * RSB + loff;

    float acc[2][4][4];
#pragma unroll
    for (int t = 0; t < 2; ++t)
#pragma unroll
        for (int i = 0; i < 4; ++i)
#pragma unroll
            for (int j = 0; j < 4; ++j) acc[t][i][j] = 0.0f;

    for (int k = 0; k < K_NBR; ++k) {
        const int buf = k & 1;
        const int kn  = k + 1;

        // prefetch h row (k+1) into regs; nbr index (k+2)
        uint4 hvn[4];
        if (kn < K_NBR) {
            const uint4* hs = g_Hh4 + (size_t)nbr_cur * 8 + hh * 4;
#pragma unroll
            for (int j = 0; j < 4; ++j) hvn[j] = hs[j];
        }
        int nbr_nx = (k + 2 < K_NBR && ok) ? nrow[k + 2] : 0;

        // MMA(k): A from smem via ldmatrix, B fragments via coalesced LDG
        const uint32_t ab = sbase + buf * A_TILE;
        const uint4* bfk = g_Bfrag + ((size_t)k * 2 + band) * 8 * 32 + lid;
#pragma unroll
        for (int kc = 0; kc < 4; ++kc) {
            uint32_t a0[4], a1[4];
            LDM_X4(a0, ab + aOff + kc * 32);
            LDM_X4(a1, ab + aOff + 16 * RSB + kc * 32);
#pragma unroll
            for (int g2 = 0; g2 < 2; ++g2) {
                uint4 bf = bfk[(kc * 2 + g2) * 32];
                MMA16816(acc[0][g2 * 2 + 0], a0, bf.x, bf.y);
                MMA16816(acc[0][g2 * 2 + 1], a0, bf.z, bf.w);
                MMA16816(acc[1][g2 * 2 + 0], a1, bf.x, bf.y);
                MMA16816(acc[1][g2 * 2 + 1], a1, bf.z, bf.w);
            }
        }

        if (kn < K_NBR) scale_sts(hvn, kn, buf ^ 1);
        nbr_cur = nbr_nx;

        __syncthreads();
    }

    // ---- epilogue: bias + leaky_relu(0.01) ----
    const int g  = lid >> 2;
    const int c0 = (lid & 3) * 2;
    const uint32_t ncol = band * 32;
#pragma unroll
    for (int t = 0; t < 2; ++t) {
        const int row0 = node0 + mrow + t * 16 + g;
        const int row1 = row0 + 8;
#pragma unroll
        for (int nt = 0; nt < 4; ++nt) {
            int col = ncol + nt * 8 + c0;
            float bx = bias[col], by = bias[col + 1];
            float2 v0 = make_float2(acc[t][nt][0] + bx, acc[t][nt][1] + by);
            float2 v1 = make_float2(acc[t][nt][2] + bx, acc[t][nt][3] + by);
            v0.x = (v0.x > 0.0f) ? v0.x : 0.01f * v0.x;
            v0.y = (v0.y > 0.0f) ? v0.y : 0.01f * v0.y;
            v1.x = (v1.x > 0.0f) ? v1.x : 0.01f * v1.x;
            v1.y = (v1.y > 0.0f) ? v1.y : 0.01f * v1.y;
            if (row0 < N_NODES) *(float2*)(out + (size_t)row0 * F_OUT + col) = v0;
            if (row1 < N_NODES) *(float2*)(out + (size_t)row1 * F_OUT + col) = v1;
        }
    }
}

// ---------------------------------------------------------------------------
// Harness entry. Inputs: h, pos, neighbor_idx, weight, bias_p
// ---------------------------------------------------------------------------
extern "C" void kernel_launch(void* const* d_in, const int* in_sizes, int n_in,
                              void* d_out, int out_size)
{
    const float* h    = (const float*)d_in[0];
    const float* pos  = (const float*)d_in[1];
    const int*   nidx = (const int*)d_in[2];
    const float* W    = (const float*)d_in[3];
    const float* bias = (const float*)d_in[4];
    float*       out  = (float*)d_out;

    static bool attr_set = false;
    if (!attr_set) {
        cudaFuncSetAttribute(gnn_mma_kernel,
                             cudaFuncAttributeMaxDynamicSharedMemorySize, SMEM_BYTES);
        attr_set = true;
    }

    convert_h_kernel<<<(N_NODES * F_IN / 4 + 255) / 256, 256>>>(h);
    frag_w_kernel<<<K_NBR, 256>>>(W);
    gnn_mma_kernel<<<NBLK, 256, SMEM_BYTES>>>(nidx, pos, bias, out);
}